// round 3
// baseline (speedup 1.0000x reference)
#include <cuda_runtime.h>
#include <cuda_bf16.h>
#include <math.h>
#include <math_constants.h>
#include <stdint.h>

#define DIM    256
#define NEMB   2048
#define NROWS  65536
#define QELEMS (NROWS * DIM)
#define GATHER_BLOCKS 16384
#define CAP    64
#define MARGIN 3.0f

// ---------------- device scratch (no allocations allowed) ----------------
__device__ float         g_embedT[NEMB * DIM];    // fp32 [j][k]
__device__ float         g_sumE2[NEMB];
__device__ __nv_bfloat16 g_embB[NEMB * DIM];      // bf16 [j][k]
__device__ int           g_idx[NROWS];
__device__ int           g_counts[NEMB];
__device__ int           g_candCnt[NROWS];
__device__ int           g_cand[NROWS * CAP];
__device__ double        g_partials[GATHER_BLOCKS];

// ---------------- helpers ----------------
__device__ __forceinline__ uint32_t smem_to_u32(const void* p) {
    uint32_t a;
    asm("{ .reg .u64 t; cvta.to.shared.u64 t, %1; cvt.u32.u64 %0, t; }"
        : "=r"(a) : "l"(p));
    return a;
}

__device__ __forceinline__ void ldsm_x4(uint32_t (&r)[4], uint32_t addr) {
    asm volatile("ldmatrix.sync.aligned.m8n8.x4.shared.b16 {%0,%1,%2,%3}, [%4];"
        : "=r"(r[0]), "=r"(r[1]), "=r"(r[2]), "=r"(r[3]) : "r"(addr));
}

__device__ __forceinline__ void mma_bf16(float (&c)[4], const uint32_t (&a)[4],
                                         uint32_t b0, uint32_t b1) {
    asm volatile(
        "mma.sync.aligned.m16n8k16.row.col.f32.bf16.bf16.f32 "
        "{%0,%1,%2,%3}, {%4,%5,%6,%7}, {%8,%9}, {%0,%1,%2,%3};"
        : "+f"(c[0]), "+f"(c[1]), "+f"(c[2]), "+f"(c[3])
        : "r"(a[0]), "r"(a[1]), "r"(a[2]), "r"(a[3]), "r"(b0), "r"(b1));
}

#define CP_ASYNC16(dst, src) \
    asm volatile("cp.async.cg.shared.global [%0], [%1], 16;" \
        :: "r"(dst), "l"(src) : "memory")
#define CP_COMMIT()  asm volatile("cp.async.commit_group;" ::: "memory")
#define CP_WAIT1()   asm volatile("cp.async.wait_group 1;" ::: "memory")
#define CP_WAIT0()   asm volatile("cp.async.wait_group 0;" ::: "memory")

// ============================================================
// Kernel 0: embedT fp32, embB bf16, ||e||^2, zero counts.
// ============================================================
__global__ void __launch_bounds__(256) prep_kernel(const float* __restrict__ embed) {
    int j = blockIdx.x * 256 + threadIdx.x;
    if (j < NEMB) {
        float s = 0.0f;
        #pragma unroll 8
        for (int d = 0; d < DIM; d++) {
            float v = embed[(size_t)d * NEMB + j];
            g_embedT[(size_t)j * DIM + d] = v;
            g_embB[(size_t)j * DIM + d]   = __float2bfloat16_rn(v);
            s = __fadd_rn(s, __fmul_rn(v, v));
        }
        g_sumE2[j]  = s;
        g_counts[j] = 0;
    }
}

// ============================================================
// Kernel 1: bf16 mma.sync distance + approx-argmin candidates.
// CTA: 64 rows. 16 N-chunks of 128 codes. 8 warps = 2 M x 4 N.
// SMEM: A 64x528B (33792) + B 2x(128x528B)=135168  -> 168960 B.
// ============================================================
#define APITCH 528
#define A_OFF  0
#define B0_OFF 33792
#define B1_OFF (33792 + 67584)
#define SMEM_DIST 168960

__global__ void __launch_bounds__(256, 1) dist_kernel(const float* __restrict__ input) {
    extern __shared__ __align__(16) char smraw[];
    const uint32_t sbase = smem_to_u32(smraw);
    const uint32_t asU   = sbase + A_OFF;

    const int tid  = threadIdx.x;
    const int wid  = tid >> 5;
    const int lane = tid & 31;
    const int warp_m = wid >> 2;     // 0..1 : 32-row strip
    const int warp_n = wid & 3;      // 0..3 : 32-col group
    const int row0 = blockIdx.x * 64;

    if (tid < 64) g_candCnt[row0 + tid] = 0;

    // ---- issue B chunk 0 (cp.async) ----
    {
        const int j0 = 0;
        const uint32_t bU = sbase + B0_OFF;
        #pragma unroll
        for (int it = 0; it < 16; it++) {
            int idx = tid + it * 256;        // 4096 vectors (128 rows x 32)
            int n = idx >> 5, v = idx & 31;
            const void* src = (const void*)(g_embB + (size_t)(j0 + n) * DIM + v * 8);
            CP_ASYNC16(bU + n * APITCH + v * 16, src);
        }
        CP_COMMIT();
    }

    // ---- load + convert A: 64 rows x 256 fp32 -> bf16 SMEM ----
    {
        const float4* in4 = (const float4*)(input + (size_t)row0 * DIM);
        #pragma unroll
        for (int it = 0; it < 16; it++) {
            int idx = tid + it * 256;        // 4096 float4 (64 rows x 64)
            int r = idx >> 6, v = idx & 63;
            float4 f = in4[idx];
            __nv_bfloat162 p0 = __floats2bfloat162_rn(f.x, f.y);
            __nv_bfloat162 p1 = __floats2bfloat162_rn(f.z, f.w);
            uint2 st;
            st.x = *reinterpret_cast<unsigned int*>(&p0);
            st.y = *reinterpret_cast<unsigned int*>(&p1);
            *(uint2*)(smraw + A_OFF + r * APITCH + v * 8) = st;
        }
    }

    float best[2][2];
    int   grow[2][2];
    #pragma unroll
    for (int mi = 0; mi < 2; mi++)
        #pragma unroll
        for (int h = 0; h < 2; h++) {
            best[mi][h] = CUDART_INF_F;
            grow[mi][h] = row0 + warp_m * 32 + mi * 16 + (lane >> 2) + h * 8;
        }

    // A fragment addresses (row = base + lane%16, khalf = lane/16)
    const int a_row_in = warp_m * 32 + (lane & 15);
    const uint32_t a_base = asU + a_row_in * APITCH + ((lane >> 4) & 1) * 16;
    // B fragment addresses (n = base + lane%8 + (lane&16)/2, khalf = (lane>>3)&1)
    const int b_row_in = warp_n * 32 + (lane & 7) + ((lane & 16) >> 1);
    const uint32_t b_off = b_row_in * APITCH + ((lane >> 3) & 1) * 16;

    #pragma unroll 1
    for (int c = 0; c < 16; c++) {
        const int j0 = c * 128;
        // prefetch chunk c+1
        if (c + 1 < 16) {
            const uint32_t bU = sbase + (((c + 1) & 1) ? B1_OFF : B0_OFF);
            #pragma unroll
            for (int it = 0; it < 16; it++) {
                int idx = tid + it * 256;
                int n = idx >> 5, v = idx & 31;
                const void* src = (const void*)(g_embB + (size_t)(j0 + 128 + n) * DIM + v * 8);
                CP_ASYNC16(bU + n * APITCH + v * 16, src);
            }
            CP_COMMIT();
            CP_WAIT1();
        } else {
            CP_WAIT0();
        }
        __syncthreads();

        const uint32_t bbase = sbase + ((c & 1) ? B1_OFF : B0_OFF) + b_off;

        float acc[2][4][4];
        #pragma unroll
        for (int mi = 0; mi < 2; mi++)
            #pragma unroll
            for (int ni = 0; ni < 4; ni++)
                #pragma unroll
                for (int q = 0; q < 4; q++) acc[mi][ni][q] = 0.0f;

        #pragma unroll 4
        for (int ks = 0; ks < 16; ks++) {
            uint32_t af[2][4], bf[2][4];
            ldsm_x4(af[0], a_base + ks * 32);
            ldsm_x4(af[1], a_base + 16 * APITCH + ks * 32);
            ldsm_x4(bf[0], bbase + ks * 32);
            ldsm_x4(bf[1], bbase + 16 * APITCH + ks * 32);
            #pragma unroll
            for (int mi = 0; mi < 2; mi++) {
                mma_bf16(acc[mi][0], af[mi], bf[0][0], bf[0][1]);
                mma_bf16(acc[mi][1], af[mi], bf[0][2], bf[0][3]);
                mma_bf16(acc[mi][2], af[mi], bf[1][0], bf[1][1]);
                mma_bf16(acc[mi][3], af[mi], bf[1][2], bf[1][3]);
            }
        }

        // ---- epilogue: key = se2 - 2*dot, running candidate collection ----
        #pragma unroll
        for (int ni = 0; ni < 4; ni++) {
            int jb = j0 + warp_n * 32 + ni * 8 + ((lane & 3) << 1);
            float se0 = __ldg(&g_sumE2[jb]);
            float se1 = __ldg(&g_sumE2[jb + 1]);
            #pragma unroll
            for (int mi = 0; mi < 2; mi++) {
                #pragma unroll
                for (int q = 0; q < 4; q++) {
                    int h = q >> 1;
                    float d = fmaf(acc[mi][ni][q], -2.0f, (q & 1) ? se1 : se0);
                    if (d < best[mi][h] + MARGIN) {
                        int g = grow[mi][h];
                        int pos = atomicAdd(&g_candCnt[g], 1);
                        if (pos < CAP) g_cand[(size_t)g * CAP + pos] = jb + (q & 1);
                        if (d < best[mi][h]) best[mi][h] = d;
                    }
                }
            }
        }
        __syncthreads();   // done reading B buf before it is overwritten
    }
}

// ============================================================
// Kernel 2: exact fp32 re-check over candidates (warp per row).
// ============================================================
__global__ void __launch_bounds__(256) recheck_kernel(
    const float* __restrict__ input, float* __restrict__ indOutF)
{
    __shared__ float xs[8][256];
    const int w = threadIdx.x >> 5, l = threadIdx.x & 31;
    const int row = blockIdx.x * 8 + w;

    const float4* xr4 = (const float4*)(input + (size_t)row * DIM);
    float4 xa = xr4[l];
    float4 xb = xr4[l + 32];
    *(float4*)&xs[w][l * 4]       = xa;
    *(float4*)&xs[w][128 + l * 4] = xb;
    __syncwarp();

    float xr[8];
    #pragma unroll
    for (int u = 0; u < 8; u++) xr[u] = xs[w][l * 8 + u];

    float p2 = 0.0f;
    #pragma unroll
    for (int u = 0; u < 8; u++) p2 = fmaf(xr[u], xr[u], p2);
    #pragma unroll
    for (int o = 16; o > 0; o >>= 1) p2 += __shfl_xor_sync(0xffffffffu, p2, o);
    const float sx2 = p2;

    const int cnt = g_candCnt[row];
    float bd = CUDART_INF_F; int bi = 0x7fffffff;

    if (cnt <= CAP) {
        for (int c = 0; c < cnt; c++) {
            int j = g_cand[(size_t)row * CAP + c];
            const float4* e4 = (const float4*)(g_embedT + (size_t)j * DIM);
            float4 e0 = e4[l * 2], e1 = e4[l * 2 + 1];
            float p = 0.0f;
            p = fmaf(xr[0], e0.x, p); p = fmaf(xr[1], e0.y, p);
            p = fmaf(xr[2], e0.z, p); p = fmaf(xr[3], e0.w, p);
            p = fmaf(xr[4], e1.x, p); p = fmaf(xr[5], e1.y, p);
            p = fmaf(xr[6], e1.z, p); p = fmaf(xr[7], e1.w, p);
            #pragma unroll
            for (int o = 16; o > 0; o >>= 1) p += __shfl_xor_sync(0xffffffffu, p, o);
            float d = __fadd_rn(__fsub_rn(sx2, __fmul_rn(2.0f, p)), __ldg(&g_sumE2[j]));
            if (d < bd || (d == bd && j < bi)) { bd = d; bi = j; }
        }
    } else {
        for (int j = l; j < NEMB; j += 32) {
            const float* e = g_embedT + (size_t)j * DIM;
            float p = 0.0f;
            for (int k = 0; k < DIM; k++) p = fmaf(xs[w][k], e[k], p);
            float d = __fadd_rn(__fsub_rn(sx2, __fmul_rn(2.0f, p)), __ldg(&g_sumE2[j]));
            if (d < bd || (d == bd && j < bi)) { bd = d; bi = j; }
        }
        #pragma unroll
        for (int o = 16; o > 0; o >>= 1) {
            float od = __shfl_xor_sync(0xffffffffu, bd, o);
            int   oi = __shfl_xor_sync(0xffffffffu, bi, o);
            if (od < bd || (od == bd && oi < bi)) { bd = od; bi = oi; }
        }
    }

    if (l == 0) {
        g_idx[row]   = bi;
        indOutF[row] = (float)bi;
        atomicAdd(&g_counts[bi], 1);
    }
}

// ============================================================
// Kernel 3: gather codes, straight-through output, diff partials.
// ============================================================
__global__ void __launch_bounds__(256) gather_kernel(
    const float* __restrict__ input, float* __restrict__ outQ)
{
    __shared__ double sred[256];
    int gid = blockIdx.x * 256 + threadIdx.x;
    int n  = gid >> 6;
    int d4 = gid & 63;
    int ind = g_idx[n];

    float4 e = *(const float4*)(g_embedT + (size_t)ind * DIM + (d4 << 2));
    float4 x = ((const float4*)input)[gid];

    float dx0 = __fsub_rn(e.x, x.x);
    float dx1 = __fsub_rn(e.y, x.y);
    float dx2 = __fsub_rn(e.z, x.z);
    float dx3 = __fsub_rn(e.w, x.w);

    float4 q;
    q.x = __fadd_rn(x.x, dx0);
    q.y = __fadd_rn(x.y, dx1);
    q.z = __fadd_rn(x.z, dx2);
    q.w = __fadd_rn(x.w, dx3);
    ((float4*)outQ)[gid] = q;

    double s = (double)__fmul_rn(dx0, dx0) + (double)__fmul_rn(dx1, dx1)
             + (double)__fmul_rn(dx2, dx2) + (double)__fmul_rn(dx3, dx3);

    sred[threadIdx.x] = s;
    __syncthreads();
    for (int o = 128; o > 0; o >>= 1) {
        if (threadIdx.x < o) sred[threadIdx.x] += sred[threadIdx.x + o];
        __syncthreads();
    }
    if (threadIdx.x == 0) g_partials[blockIdx.x] = sred[0];
}

// ============================================================
// Kernel 4: finalize diff + perplexity.
// ============================================================
__global__ void __launch_bounds__(1024) finalize_kernel(
    float* __restrict__ outDiff, float* __restrict__ outPerp)
{
    __shared__ double sred[1024];
    int tid = threadIdx.x;

    double s = 0.0;
    for (int i = tid; i < GATHER_BLOCKS; i += 1024) s += g_partials[i];
    sred[tid] = s;
    __syncthreads();
    for (int o = 512; o > 0; o >>= 1) {
        if (tid < o) sred[tid] += sred[tid + o];
        __syncthreads();
    }
    if (tid == 0) *outDiff = (float)(sred[0] / (double)QELEMS);
    __syncthreads();

    double ps = 0.0;
    for (int j = tid; j < NEMB; j += 1024) {
        float p  = (float)g_counts[j] * (1.0f / 65536.0f);
        float cl = fmaxf(p, 1e-7f);
        ps += (double)__fmul_rn(p, logf(cl));
    }
    sred[tid] = ps;
    __syncthreads();
    for (int o = 512; o > 0; o >>= 1) {
        if (tid < o) sred[tid] += sred[tid + o];
        __syncthreads();
    }
    if (tid == 0) *outPerp = expf((float)(-sred[0]));
}

// ============================================================
// Output layout (float32): [quantize_st | diff | embed_ind | perplexity]
// ============================================================
extern "C" void kernel_launch(void* const* d_in, const int* in_sizes, int n_in,
                              void* d_out, int out_size) {
    const float* input = (const float*)d_in[0];
    const float* embed = (const float*)d_in[1];
    float* out     = (float*)d_out;
    float* outQ    = out;
    float* outDiff = out + QELEMS;
    float* outInd  = out + QELEMS + 1;
    float* outPerp = out + QELEMS + 1 + NROWS;

    cudaFuncSetAttribute(dist_kernel,
                         cudaFuncAttributeMaxDynamicSharedMemorySize, SMEM_DIST);

    prep_kernel<<<8, 256>>>(embed);
    dist_kernel<<<NROWS / 64, 256, SMEM_DIST>>>(input);
    recheck_kernel<<<NROWS / 8, 256>>>(input, outInd);
    gather_kernel<<<GATHER_BLOCKS, 256>>>(input, outQ);
    finalize_kernel<<<1, 1024>>>(outDiff, outPerp);
}

// round 4
// speedup vs baseline: 157.0675x; 157.0675x over previous
#include <cuda_runtime.h>
#include <cuda_bf16.h>
#include <math.h>
#include <math_constants.h>
#include <stdint.h>

#define DIM    256
#define NEMB   2048
#define NROWS  65536
#define QELEMS (NROWS * DIM)
#define GATHER_BLOCKS 8192
#define CAP    64
#define MARGIN 3.0f

// ---------------- device scratch (no allocations allowed) ----------------
__device__ float         g_embedT[NEMB * DIM];    // fp32 [j][k]
__device__ float         g_sumE2[NEMB];
__device__ __nv_bfloat16 g_embB[NEMB * DIM];      // bf16 [j][k]
__device__ int           g_idx[NROWS];
__device__ int           g_counts[NEMB];
__device__ int           g_candCnt[NROWS];
__device__ int           g_cand[NROWS * CAP];
__device__ double        g_partials[GATHER_BLOCKS];

// ---------------- helpers ----------------
__device__ __forceinline__ uint32_t smem_to_u32(const void* p) {
    uint32_t a;
    asm("{ .reg .u64 t; cvta.to.shared.u64 t, %1; cvt.u32.u64 %0, t; }"
        : "=r"(a) : "l"(p));
    return a;
}
__device__ __forceinline__ uint32_t fenc(float f) {       // monotonic float->uint
    uint32_t u = __float_as_uint(f);
    return u ^ ((u >> 31) ? 0xFFFFFFFFu : 0x80000000u);
}
__device__ __forceinline__ float fdec(uint32_t u) {
    return __uint_as_float(u ^ ((u & 0x80000000u) ? 0x80000000u : 0xFFFFFFFFu));
}

__device__ __forceinline__ void ldsm_x4(uint32_t (&r)[4], uint32_t addr) {
    asm volatile("ldmatrix.sync.aligned.m8n8.x4.shared.b16 {%0,%1,%2,%3}, [%4];"
        : "=r"(r[0]), "=r"(r[1]), "=r"(r[2]), "=r"(r[3]) : "r"(addr));
}

__device__ __forceinline__ void mma_bf16(float (&c)[4], const uint32_t (&a)[4],
                                         uint32_t b0, uint32_t b1) {
    asm volatile(
        "mma.sync.aligned.m16n8k16.row.col.f32.bf16.bf16.f32 "
        "{%0,%1,%2,%3}, {%4,%5,%6,%7}, {%8,%9}, {%0,%1,%2,%3};"
        : "+f"(c[0]), "+f"(c[1]), "+f"(c[2]), "+f"(c[3])
        : "r"(a[0]), "r"(a[1]), "r"(a[2]), "r"(a[3]), "r"(b0), "r"(b1));
}

#define CP_ASYNC16(dst, src) \
    asm volatile("cp.async.cg.shared.global [%0], [%1], 16;" \
        :: "r"(dst), "l"(src) : "memory")
#define CP_COMMIT()  asm volatile("cp.async.commit_group;" ::: "memory")
#define CP_WAIT1()   asm volatile("cp.async.wait_group 1;" ::: "memory")
#define CP_WAIT0()   asm volatile("cp.async.wait_group 0;" ::: "memory")

// ============================================================
// Kernel 0: embedT fp32, embB bf16, ||e||^2, zero counts.
// ============================================================
__global__ void __launch_bounds__(256) prep_kernel(const float* __restrict__ embed) {
    int j = blockIdx.x * 256 + threadIdx.x;
    if (j < NEMB) {
        float s = 0.0f;
        #pragma unroll 8
        for (int d = 0; d < DIM; d++) {
            float v = embed[(size_t)d * NEMB + j];
            g_embedT[(size_t)j * DIM + d] = v;
            g_embB[(size_t)j * DIM + d]   = __float2bfloat16_rn(v);
            s = __fadd_rn(s, __fmul_rn(v, v));
        }
        g_sumE2[j]  = s;
        g_counts[j] = 0;
    }
}

// ============================================================
// Kernel 1: bf16 mma.sync distance + shared-row-best candidates.
// CTA: 64 rows. 16 N-chunks of 128 codes. 8 warps = 2 M x 4 N.
// ============================================================
#define APITCH 528
#define A_OFF  0
#define B0_OFF 33792
#define B1_OFF (33792 + 67584)
#define RB_OFF (33792 + 2 * 67584)          // 64 uints row-best
#define SMEM_DIST (RB_OFF + 256)

__global__ void __launch_bounds__(256, 1) dist_kernel(const float* __restrict__ input) {
    extern __shared__ __align__(16) char smraw[];
    const uint32_t sbase = smem_to_u32(smraw);
    const uint32_t asU   = sbase + A_OFF;
    unsigned int* sRowBest = (unsigned int*)(smraw + RB_OFF);

    const int tid  = threadIdx.x;
    const int wid  = tid >> 5;
    const int lane = tid & 31;
    const int warp_m = wid >> 2;     // 0..1 : 32-row strip
    const int warp_n = wid & 3;      // 0..3 : 32-col group
    const int row0 = blockIdx.x * 64;

    if (tid < 64) {
        g_candCnt[row0 + tid] = 0;
        sRowBest[tid] = 0xFFFFFFFFu;
    }

    // ---- issue B chunk 0 (cp.async) ----
    {
        const uint32_t bU = sbase + B0_OFF;
        #pragma unroll
        for (int it = 0; it < 16; it++) {
            int idx = tid + it * 256;        // 4096 vectors (128 rows x 32)
            int n = idx >> 5, v = idx & 31;
            const void* src = (const void*)(g_embB + (size_t)n * DIM + v * 8);
            CP_ASYNC16(bU + n * APITCH + v * 16, src);
        }
        CP_COMMIT();
    }

    // ---- load + convert A: 64 rows x 256 fp32 -> bf16 SMEM ----
    {
        const float4* in4 = (const float4*)(input + (size_t)row0 * DIM);
        #pragma unroll
        for (int it = 0; it < 16; it++) {
            int idx = tid + it * 256;        // 4096 float4 (64 rows x 64)
            int r = idx >> 6, v = idx & 63;
            float4 f = in4[idx];
            __nv_bfloat162 p0 = __floats2bfloat162_rn(f.x, f.y);
            __nv_bfloat162 p1 = __floats2bfloat162_rn(f.z, f.w);
            uint2 st;
            st.x = *reinterpret_cast<unsigned int*>(&p0);
            st.y = *reinterpret_cast<unsigned int*>(&p1);
            *(uint2*)(smraw + A_OFF + r * APITCH + v * 8) = st;
        }
    }

    // local row ids for the 4 (mi,h) accumulator rows this thread owns
    int lrow[2][2];
    #pragma unroll
    for (int mi = 0; mi < 2; mi++)
        #pragma unroll
        for (int h = 0; h < 2; h++)
            lrow[mi][h] = warp_m * 32 + mi * 16 + (lane >> 2) + h * 8;

    // A fragment addresses
    const int a_row_in = warp_m * 32 + (lane & 15);
    const uint32_t a_base = asU + a_row_in * APITCH + ((lane >> 4) & 1) * 16;
    // B fragment addresses
    const int b_row_in = warp_n * 32 + (lane & 7) + ((lane & 16) >> 1);
    const uint32_t b_off = b_row_in * APITCH + ((lane >> 3) & 1) * 16;

    #pragma unroll 1
    for (int c = 0; c < 16; c++) {
        const int j0 = c * 128;
        if (c + 1 < 16) {
            const uint32_t bU = sbase + (((c + 1) & 1) ? B1_OFF : B0_OFF);
            #pragma unroll
            for (int it = 0; it < 16; it++) {
                int idx = tid + it * 256;
                int n = idx >> 5, v = idx & 31;
                const void* src = (const void*)(g_embB + (size_t)(j0 + 128 + n) * DIM + v * 8);
                CP_ASYNC16(bU + n * APITCH + v * 16, src);
            }
            CP_COMMIT();
            CP_WAIT1();
        } else {
            CP_WAIT0();
        }
        __syncthreads();

        const uint32_t bbase = sbase + ((c & 1) ? B1_OFF : B0_OFF) + b_off;

        float acc[2][4][4];
        #pragma unroll
        for (int mi = 0; mi < 2; mi++)
            #pragma unroll
            for (int ni = 0; ni < 4; ni++)
                #pragma unroll
                for (int q = 0; q < 4; q++) acc[mi][ni][q] = 0.0f;

        #pragma unroll 4
        for (int ks = 0; ks < 16; ks++) {
            uint32_t af[2][4], bf[2][4];
            ldsm_x4(af[0], a_base + ks * 32);
            ldsm_x4(af[1], a_base + 16 * APITCH + ks * 32);
            ldsm_x4(bf[0], bbase + ks * 32);
            ldsm_x4(bf[1], bbase + 16 * APITCH + ks * 32);
            #pragma unroll
            for (int mi = 0; mi < 2; mi++) {
                mma_bf16(acc[mi][0], af[mi], bf[0][0], bf[0][1]);
                mma_bf16(acc[mi][1], af[mi], bf[0][2], bf[0][3]);
                mma_bf16(acc[mi][2], af[mi], bf[1][0], bf[1][1]);
                mma_bf16(acc[mi][3], af[mi], bf[1][2], bf[1][3]);
            }
        }

        // ---- turn dots into keys d = se2 - 2*dot (in place); local minima ----
        float lmin[2][2] = {{CUDART_INF_F, CUDART_INF_F},
                            {CUDART_INF_F, CUDART_INF_F}};
        #pragma unroll
        for (int ni = 0; ni < 4; ni++) {
            int jb = j0 + warp_n * 32 + ni * 8 + ((lane & 3) << 1);
            float se0 = __ldg(&g_sumE2[jb]);
            float se1 = __ldg(&g_sumE2[jb + 1]);
            #pragma unroll
            for (int mi = 0; mi < 2; mi++) {
                #pragma unroll
                for (int q = 0; q < 4; q++) {
                    float d = fmaf(acc[mi][ni][q], -2.0f, (q & 1) ? se1 : se0);
                    acc[mi][ni][q] = d;
                    int h = q >> 1;
                    lmin[mi][h] = fminf(lmin[mi][h], d);
                }
            }
        }
        // publish chunk minima to shared row-best
        #pragma unroll
        for (int mi = 0; mi < 2; mi++)
            #pragma unroll
            for (int h = 0; h < 2; h++)
                atomicMin(&sRowBest[lrow[mi][h]], fenc(lmin[mi][h]));
        __syncthreads();

        // margin test vs row-global running best, append candidates
        #pragma unroll
        for (int mi = 0; mi < 2; mi++) {
            #pragma unroll
            for (int h = 0; h < 2; h++) {
                float rb = fdec(sRowBest[lrow[mi][h]]) + MARGIN;
                int g = row0 + lrow[mi][h];
                #pragma unroll
                for (int ni = 0; ni < 4; ni++) {
                    #pragma unroll
                    for (int qq = 0; qq < 2; qq++) {
                        int q = h * 2 + qq;
                        float d = acc[mi][ni][q];
                        if (d < rb) {
                            int pos = atomicAdd(&g_candCnt[g], 1);
                            if (pos < CAP)
                                g_cand[(size_t)g * CAP + pos] =
                                    j0 + warp_n * 32 + ni * 8 + ((lane & 3) << 1) + qq;
                        }
                    }
                }
            }
        }
        __syncthreads();   // done reading B buf + sRowBest stable
    }
}

// ============================================================
// Kernel 2: exact fp32 re-check over candidates (warp per row).
// ============================================================
__global__ void __launch_bounds__(256) recheck_kernel(
    const float* __restrict__ input, float* __restrict__ indOutF)
{
    __shared__ float xs[8][256];
    const int w = threadIdx.x >> 5, l = threadIdx.x & 31;
    const int row = blockIdx.x * 8 + w;

    const float4* xr4 = (const float4*)(input + (size_t)row * DIM);
    float4 xa = xr4[l];
    float4 xb = xr4[l + 32];
    *(float4*)&xs[w][l * 4]       = xa;
    *(float4*)&xs[w][128 + l * 4] = xb;
    __syncwarp();

    float xr[8];
    #pragma unroll
    for (int u = 0; u < 8; u++) xr[u] = xs[w][l * 8 + u];

    float p2 = 0.0f;
    #pragma unroll
    for (int u = 0; u < 8; u++) p2 = fmaf(xr[u], xr[u], p2);
    #pragma unroll
    for (int o = 16; o > 0; o >>= 1) p2 += __shfl_xor_sync(0xffffffffu, p2, o);
    const float sx2 = p2;

    const int cnt = g_candCnt[row];
    float bd = CUDART_INF_F; int bi = 0x7fffffff;

    const int limit = (cnt <= CAP) ? cnt : NEMB;
    for (int c = 0; c < limit; c++) {
        int j = (cnt <= CAP) ? g_cand[(size_t)row * CAP + c] : c;
        const float4* e4 = (const float4*)(g_embedT + (size_t)j * DIM);
        float4 e0 = e4[l * 2], e1 = e4[l * 2 + 1];
        float p = 0.0f;
        p = fmaf(xr[0], e0.x, p); p = fmaf(xr[1], e0.y, p);
        p = fmaf(xr[2], e0.z, p); p = fmaf(xr[3], e0.w, p);
        p = fmaf(xr[4], e1.x, p); p = fmaf(xr[5], e1.y, p);
        p = fmaf(xr[6], e1.z, p); p = fmaf(xr[7], e1.w, p);
        #pragma unroll
        for (int o = 16; o > 0; o >>= 1) p += __shfl_xor_sync(0xffffffffu, p, o);
        float d = __fadd_rn(__fsub_rn(sx2, __fmul_rn(2.0f, p)), __ldg(&g_sumE2[j]));
        if (d < bd || (d == bd && j < bi)) { bd = d; bi = j; }
    }

    if (l == 0) {
        g_idx[row]   = bi;
        indOutF[row] = (float)bi;
        atomicAdd(&g_counts[bi], 1);
    }
}

// ============================================================
// Kernel 3: gather codes, STE output, diff partials (8/thread).
// ============================================================
__global__ void __launch_bounds__(256) gather_kernel(
    const float* __restrict__ input, float* __restrict__ outQ)
{
    __shared__ double wsum[8];
    const int t = blockIdx.x * 256 + threadIdx.x;   // handles float4 2t, 2t+1
    const int n = t >> 5;
    const int ind = g_idx[n];
    const int v0 = (t & 31) * 2;                     // float4 idx within row

    const float4* erow = (const float4*)(g_embedT + (size_t)ind * DIM);
    const float4* xrow = (const float4*)(input + (size_t)n * DIM);
    float4* qrow = (float4*)(outQ + (size_t)n * DIM);

    double s = 0.0;
    #pragma unroll
    for (int u = 0; u < 2; u++) {
        float4 e = __ldg(&erow[v0 + u]);
        float4 x = xrow[v0 + u];
        float dx0 = __fsub_rn(e.x, x.x);
        float dx1 = __fsub_rn(e.y, x.y);
        float dx2 = __fsub_rn(e.z, x.z);
        float dx3 = __fsub_rn(e.w, x.w);
        float4 q;
        q.x = __fadd_rn(x.x, dx0);
        q.y = __fadd_rn(x.y, dx1);
        q.z = __fadd_rn(x.z, dx2);
        q.w = __fadd_rn(x.w, dx3);
        qrow[v0 + u] = q;
        s += (double)__fmul_rn(dx0, dx0) + (double)__fmul_rn(dx1, dx1)
           + (double)__fmul_rn(dx2, dx2) + (double)__fmul_rn(dx3, dx3);
    }

    #pragma unroll
    for (int o = 16; o > 0; o >>= 1) s += __shfl_xor_sync(0xffffffffu, s, o);
    if ((threadIdx.x & 31) == 0) wsum[threadIdx.x >> 5] = s;
    __syncthreads();
    if (threadIdx.x == 0) {
        double acc = 0.0;
        #pragma unroll
        for (int i = 0; i < 8; i++) acc += wsum[i];
        g_partials[blockIdx.x] = acc;
    }
}

// ============================================================
// Kernel 4: finalize diff + perplexity.
// ============================================================
__global__ void __launch_bounds__(1024) finalize_kernel(
    float* __restrict__ outDiff, float* __restrict__ outPerp)
{
    __shared__ double sred[1024];
    int tid = threadIdx.x;

    double s = 0.0;
    for (int i = tid; i < GATHER_BLOCKS; i += 1024) s += g_partials[i];
    sred[tid] = s;
    __syncthreads();
    for (int o = 512; o > 0; o >>= 1) {
        if (tid < o) sred[tid] += sred[tid + o];
        __syncthreads();
    }
    if (tid == 0) *outDiff = (float)(sred[0] / (double)QELEMS);
    __syncthreads();

    double ps = 0.0;
    for (int j = tid; j < NEMB; j += 1024) {
        float p  = (float)g_counts[j] * (1.0f / 65536.0f);
        float cl = fmaxf(p, 1e-7f);
        ps += (double)__fmul_rn(p, logf(cl));
    }
    sred[tid] = ps;
    __syncthreads();
    for (int o = 512; o > 0; o >>= 1) {
        if (tid < o) sred[tid] += sred[tid + o];
        __syncthreads();
    }
    if (tid == 0) *outPerp = expf((float)(-sred[0]));
}

// ============================================================
// Output layout (float32): [quantize_st | diff | embed_ind | perplexity]
// ============================================================
extern "C" void kernel_launch(void* const* d_in, const int* in_sizes, int n_in,
                              void* d_out, int out_size) {
    const float* input = (const float*)d_in[0];
    const float* embed = (const float*)d_in[1];
    float* out     = (float*)d_out;
    float* outQ    = out;
    float* outDiff = out + QELEMS;
    float* outInd  = out + QELEMS + 1;
    float* outPerp = out + QELEMS + 1 + NROWS;

    cudaFuncSetAttribute(dist_kernel,
                         cudaFuncAttributeMaxDynamicSharedMemorySize, SMEM_DIST);

    prep_kernel<<<8, 256>>>(embed);
    dist_kernel<<<NROWS / 64, 256, SMEM_DIST>>>(input);
    recheck_kernel<<<NROWS / 8, 256>>>(input, outInd);
    gather_kernel<<<GATHER_BLOCKS, 256>>>(input, outQ);
    finalize_kernel<<<1, 1024>>>(outDiff, outPerp);
}

// round 5
// speedup vs baseline: 186.4313x; 1.1870x over previous
#include <cuda_runtime.h>
#include <cuda_bf16.h>
#include <math.h>
#include <math_constants.h>
#include <stdint.h>

#define DIM    256
#define NEMB   2048
#define NROWS  65536
#define QELEMS (NROWS * DIM)
#define GATHER_BLOCKS 4096
#define CAP    64
#define MARGIN 3.0f

#define M_CTA  256
#define CHUNK  64
#define NCHUNK (NEMB / CHUNK)     // 32

// ---------------- device scratch (no allocations allowed) ----------------
__device__ float         g_embedT[NEMB * DIM];    // fp32 [j][k]
__device__ float         g_sumE2[NEMB];
__device__ __nv_bfloat16 g_embB[NEMB * DIM];      // bf16 [j][k]
__device__ int           g_idx[NROWS];
__device__ int           g_counts[NEMB];
__device__ int           g_candCnt[NROWS];
__device__ int           g_cand[NROWS * CAP];
__device__ double        g_partials[GATHER_BLOCKS];

// ---------------- helpers ----------------
__device__ __forceinline__ uint32_t smem_to_u32(const void* p) {
    uint32_t a;
    asm("{ .reg .u64 t; cvta.to.shared.u64 t, %1; cvt.u32.u64 %0, t; }"
        : "=r"(a) : "l"(p));
    return a;
}
__device__ __forceinline__ uint32_t fenc(float f) {
    uint32_t u = __float_as_uint(f);
    return u ^ ((u >> 31) ? 0xFFFFFFFFu : 0x80000000u);
}
__device__ __forceinline__ float fdec(uint32_t u) {
    return __uint_as_float(u ^ ((u & 0x80000000u) ? 0x80000000u : 0xFFFFFFFFu));
}

__device__ __forceinline__ void ldsm_x4(uint32_t (&r)[4], uint32_t addr) {
    asm volatile("ldmatrix.sync.aligned.m8n8.x4.shared.b16 {%0,%1,%2,%3}, [%4];"
        : "=r"(r[0]), "=r"(r[1]), "=r"(r[2]), "=r"(r[3]) : "r"(addr));
}

__device__ __forceinline__ void mma_bf16(float (&c)[4], const uint32_t (&a)[4],
                                         uint32_t b0, uint32_t b1) {
    asm volatile(
        "mma.sync.aligned.m16n8k16.row.col.f32.bf16.bf16.f32 "
        "{%0,%1,%2,%3}, {%4,%5,%6,%7}, {%8,%9}, {%0,%1,%2,%3};"
        : "+f"(c[0]), "+f"(c[1]), "+f"(c[2]), "+f"(c[3])
        : "r"(a[0]), "r"(a[1]), "r"(a[2]), "r"(a[3]), "r"(b0), "r"(b1));
}

#define CP_ASYNC16(dst, src) \
    asm volatile("cp.async.cg.shared.global [%0], [%1], 16;" \
        :: "r"(dst), "l"(src) : "memory")
#define CP_COMMIT()  asm volatile("cp.async.commit_group;" ::: "memory")
#define CP_WAIT1()   asm volatile("cp.async.wait_group 1;" ::: "memory")
#define CP_WAIT0()   asm volatile("cp.async.wait_group 0;" ::: "memory")

// ============================================================
// Kernel 0: embedT fp32, embB bf16, ||e||^2, zero counts.
// 64 blocks x 256 threads = (32 j) x (8 d-segments of 32).
// ============================================================
__global__ void __launch_bounds__(256) prep_kernel(const float* __restrict__ embed) {
    __shared__ float psum[8][32];
    const int jl  = threadIdx.x & 31;
    const int seg = threadIdx.x >> 5;
    const int j   = blockIdx.x * 32 + jl;
    const int d0  = seg * 32;

    float s = 0.0f;
    #pragma unroll 8
    for (int dd = 0; dd < 32; dd++) {
        int d = d0 + dd;
        float v = embed[(size_t)d * NEMB + j];      // coalesced over j
        g_embedT[(size_t)j * DIM + d] = v;
        g_embB[(size_t)j * DIM + d]   = __float2bfloat16_rn(v);
        s = __fadd_rn(s, __fmul_rn(v, v));
    }
    psum[seg][jl] = s;
    __syncthreads();
    if (seg == 0) {
        float t = 0.0f;
        #pragma unroll
        for (int q = 0; q < 8; q++) t += psum[q][jl];
        g_sumE2[j]  = t;
        g_counts[j] = 0;
    }
}

// ============================================================
// Kernel 1: bf16 mma.sync distance + shared-row-best candidates.
// CTA: 256 rows. 32 N-chunks of 64 codes. 8 warps = 4 M x 2 N.
// Warp tile: 64 rows x 32 cols.
// ============================================================
#define APITCH 528
#define A_OFF  0
#define B0_OFF (M_CTA * APITCH)                     // 135168
#define B1_OFF (B0_OFF + CHUNK * APITCH)            // +33792
#define RB_OFF (B1_OFF + CHUNK * APITCH)            // +33792
#define SMEM_DIST (RB_OFF + M_CTA * 4)              // 203776 + 1024 = 203776? (RB 1024)

__global__ void __launch_bounds__(256, 1) dist_kernel(const float* __restrict__ input) {
    extern __shared__ __align__(16) char smraw[];
    const uint32_t sbase = smem_to_u32(smraw);
    const uint32_t asU   = sbase + A_OFF;
    unsigned int* sRowBest = (unsigned int*)(smraw + RB_OFF);

    const int tid  = threadIdx.x;
    const int wid  = tid >> 5;
    const int lane = tid & 31;
    const int warp_m = wid >> 1;     // 0..3 : 64-row strip
    const int warp_n = wid & 1;      // 0..1 : 32-col group
    const int row0 = blockIdx.x * M_CTA;

    g_candCnt[row0 + tid] = 0;
    sRowBest[tid] = 0xFFFFFFFFu;

    // ---- issue B chunk 0 (cp.async): 64 codes x 512B = 2048 vec16 ----
    {
        const uint32_t bU = sbase + B0_OFF;
        #pragma unroll
        for (int it = 0; it < 8; it++) {
            int idx = tid + it * 256;
            int n = idx >> 5, v = idx & 31;
            const void* src = (const void*)(g_embB + (size_t)n * DIM + v * 8);
            CP_ASYNC16(bU + n * APITCH + v * 16, src);
        }
        CP_COMMIT();
    }

    // ---- load + convert A: 256 rows x 256 fp32 -> bf16 SMEM ----
    {
        const float4* in4 = (const float4*)(input + (size_t)row0 * DIM);
        #pragma unroll
        for (int it = 0; it < 64; it++) {
            int idx = tid + it * 256;        // 16384 float4
            int r = idx >> 6, v = idx & 63;
            float4 f = in4[idx];
            __nv_bfloat162 p0 = __floats2bfloat162_rn(f.x, f.y);
            __nv_bfloat162 p1 = __floats2bfloat162_rn(f.z, f.w);
            uint2 st;
            st.x = *reinterpret_cast<unsigned int*>(&p0);
            st.y = *reinterpret_cast<unsigned int*>(&p1);
            *(uint2*)(smraw + A_OFF + r * APITCH + v * 8) = st;
        }
    }

    // rows owned by this thread: lrow[mt][h]
    int lrow[4][2];
    #pragma unroll
    for (int mt = 0; mt < 4; mt++)
        #pragma unroll
        for (int h = 0; h < 2; h++)
            lrow[mt][h] = warp_m * 64 + mt * 16 + (lane >> 2) + h * 8;

    // A fragment base (per mt add mt*16*APITCH)
    const uint32_t a_base = asU + (warp_m * 64 + (lane & 15)) * APITCH
                          + ((lane >> 4) & 1) * 16;
    // B fragment base (per 16-code group add 16*APITCH)
    const uint32_t b_off = (warp_n * 32 + (lane & 7) + ((lane & 16) >> 1)) * APITCH
                         + ((lane >> 3) & 1) * 16;

    #pragma unroll 1
    for (int c = 0; c < NCHUNK; c++) {
        const int j0 = c * CHUNK;
        if (c + 1 < NCHUNK) {
            const uint32_t bU = sbase + (((c + 1) & 1) ? B1_OFF : B0_OFF);
            #pragma unroll
            for (int it = 0; it < 8; it++) {
                int idx = tid + it * 256;
                int n = idx >> 5, v = idx & 31;
                const void* src = (const void*)(g_embB + (size_t)(j0 + CHUNK + n) * DIM + v * 8);
                CP_ASYNC16(bU + n * APITCH + v * 16, src);
            }
            CP_COMMIT();
            CP_WAIT1();
        } else {
            CP_WAIT0();
        }
        __syncthreads();

        const uint32_t bbase = sbase + ((c & 1) ? B1_OFF : B0_OFF) + b_off;

        float acc[4][4][4];
        #pragma unroll
        for (int mt = 0; mt < 4; mt++)
            #pragma unroll
            for (int ni = 0; ni < 4; ni++)
                #pragma unroll
                for (int q = 0; q < 4; q++) acc[mt][ni][q] = 0.0f;

        #pragma unroll 2
        for (int ks = 0; ks < 16; ks++) {
            uint32_t af[4][4], bf[2][4];
            ldsm_x4(bf[0], bbase + ks * 32);
            ldsm_x4(bf[1], bbase + 16 * APITCH + ks * 32);
            #pragma unroll
            for (int mt = 0; mt < 4; mt++)
                ldsm_x4(af[mt], a_base + mt * 16 * APITCH + ks * 32);
            #pragma unroll
            for (int mt = 0; mt < 4; mt++) {
                mma_bf16(acc[mt][0], af[mt], bf[0][0], bf[0][1]);
                mma_bf16(acc[mt][1], af[mt], bf[0][2], bf[0][3]);
                mma_bf16(acc[mt][2], af[mt], bf[1][0], bf[1][1]);
                mma_bf16(acc[mt][3], af[mt], bf[1][2], bf[1][3]);
            }
        }

        // ---- keys d = se2 - 2*dot (in place); per-(mt,h) minima ----
        float lmin[4][2];
        #pragma unroll
        for (int mt = 0; mt < 4; mt++)
            #pragma unroll
            for (int h = 0; h < 2; h++) lmin[mt][h] = CUDART_INF_F;

        #pragma unroll
        for (int ni = 0; ni < 4; ni++) {
            int jb = j0 + warp_n * 32 + ni * 8 + ((lane & 3) << 1);
            float se0 = __ldg(&g_sumE2[jb]);
            float se1 = __ldg(&g_sumE2[jb + 1]);
            #pragma unroll
            for (int mt = 0; mt < 4; mt++) {
                #pragma unroll
                for (int q = 0; q < 4; q++) {
                    float d = fmaf(acc[mt][ni][q], -2.0f, (q & 1) ? se1 : se0);
                    acc[mt][ni][q] = d;
                    lmin[mt][q >> 1] = fminf(lmin[mt][q >> 1], d);
                }
            }
        }
        #pragma unroll
        for (int mt = 0; mt < 4; mt++)
            #pragma unroll
            for (int h = 0; h < 2; h++)
                atomicMin(&sRowBest[lrow[mt][h]], fenc(lmin[mt][h]));
        __syncthreads();

        // margin test vs row-global running best, append candidates
        #pragma unroll
        for (int mt = 0; mt < 4; mt++) {
            #pragma unroll
            for (int h = 0; h < 2; h++) {
                float rb = fdec(sRowBest[lrow[mt][h]]) + MARGIN;
                int g = row0 + lrow[mt][h];
                #pragma unroll
                for (int ni = 0; ni < 4; ni++) {
                    #pragma unroll
                    for (int qq = 0; qq < 2; qq++) {
                        float d = acc[mt][ni][h * 2 + qq];
                        if (d < rb) {
                            int pos = atomicAdd(&g_candCnt[g], 1);
                            if (pos < CAP)
                                g_cand[(size_t)g * CAP + pos] =
                                    j0 + warp_n * 32 + ni * 8 + ((lane & 3) << 1) + qq;
                        }
                    }
                }
            }
        }
        __syncthreads();
    }
}

// ============================================================
// Kernel 2: exact fp32 re-check over candidates (warp per row).
// ============================================================
__global__ void __launch_bounds__(256) recheck_kernel(
    const float* __restrict__ input, float* __restrict__ indOutF)
{
    __shared__ float xs[8][256];
    const int w = threadIdx.x >> 5, l = threadIdx.x & 31;
    const int row = blockIdx.x * 8 + w;

    const float4* xr4 = (const float4*)(input + (size_t)row * DIM);
    float4 xa = xr4[l];
    float4 xb = xr4[l + 32];
    *(float4*)&xs[w][l * 4]       = xa;
    *(float4*)&xs[w][128 + l * 4] = xb;
    __syncwarp();

    float xr[8];
    #pragma unroll
    for (int u = 0; u < 8; u++) xr[u] = xs[w][l * 8 + u];

    float p2 = 0.0f;
    #pragma unroll
    for (int u = 0; u < 8; u++) p2 = fmaf(xr[u], xr[u], p2);
    #pragma unroll
    for (int o = 16; o > 0; o >>= 1) p2 += __shfl_xor_sync(0xffffffffu, p2, o);
    const float sx2 = p2;

    const int cnt = g_candCnt[row];
    float bd = CUDART_INF_F; int bi = 0x7fffffff;

    const int limit = (cnt <= CAP) ? cnt : NEMB;
    for (int c = 0; c < limit; c++) {
        int j = (cnt <= CAP) ? g_cand[(size_t)row * CAP + c] : c;
        const float4* e4 = (const float4*)(g_embedT + (size_t)j * DIM);
        float4 e0 = e4[l * 2], e1 = e4[l * 2 + 1];
        float p = 0.0f;
        p = fmaf(xr[0], e0.x, p); p = fmaf(xr[1], e0.y, p);
        p = fmaf(xr[2], e0.z, p); p = fmaf(xr[3], e0.w, p);
        p = fmaf(xr[4], e1.x, p); p = fmaf(xr[5], e1.y, p);
        p = fmaf(xr[6], e1.z, p); p = fmaf(xr[7], e1.w, p);
        #pragma unroll
        for (int o = 16; o > 0; o >>= 1) p += __shfl_xor_sync(0xffffffffu, p, o);
        float d = __fadd_rn(__fsub_rn(sx2, __fmul_rn(2.0f, p)), __ldg(&g_sumE2[j]));
        if (d < bd || (d == bd && j < bi)) { bd = d; bi = j; }
    }

    if (l == 0) {
        g_idx[row]   = bi;
        indOutF[row] = (float)bi;
        atomicAdd(&g_counts[bi], 1);
    }
}

// ============================================================
// Kernel 3: gather codes, STE output, diff partials (16 f/thread).
// ============================================================
__global__ void __launch_bounds__(256) gather_kernel(
    const float* __restrict__ input, float* __restrict__ outQ)
{
    __shared__ double wsum[8];
    const int t = blockIdx.x * 256 + threadIdx.x;   // handles float4 4t..4t+3
    const int n = t >> 4;                            // 16 threads per row
    const int ind = g_idx[n];
    const int v0 = (t & 15) * 4;

    const float4* erow = (const float4*)(g_embedT + (size_t)ind * DIM);
    const float4* xrow = (const float4*)(input + (size_t)n * DIM);
    float4* qrow = (float4*)(outQ + (size_t)n * DIM);

    float4 e[4], x[4];
    #pragma unroll
    for (int u = 0; u < 4; u++) e[u] = __ldg(&erow[v0 + u]);
    #pragma unroll
    for (int u = 0; u < 4; u++) x[u] = xrow[v0 + u];

    double s = 0.0;
    #pragma unroll
    for (int u = 0; u < 4; u++) {
        float dx0 = __fsub_rn(e[u].x, x[u].x);
        float dx1 = __fsub_rn(e[u].y, x[u].y);
        float dx2 = __fsub_rn(e[u].z, x[u].z);
        float dx3 = __fsub_rn(e[u].w, x[u].w);
        float4 q;
        q.x = __fadd_rn(x[u].x, dx0);
        q.y = __fadd_rn(x[u].y, dx1);
        q.z = __fadd_rn(x[u].z, dx2);
        q.w = __fadd_rn(x[u].w, dx3);
        qrow[v0 + u] = q;
        s += (double)__fmul_rn(dx0, dx0) + (double)__fmul_rn(dx1, dx1)
           + (double)__fmul_rn(dx2, dx2) + (double)__fmul_rn(dx3, dx3);
    }

    #pragma unroll
    for (int o = 16; o > 0; o >>= 1) s += __shfl_xor_sync(0xffffffffu, s, o);
    if ((threadIdx.x & 31) == 0) wsum[threadIdx.x >> 5] = s;
    __syncthreads();
    if (threadIdx.x == 0) {
        double acc = 0.0;
        #pragma unroll
        for (int i = 0; i < 8; i++) acc += wsum[i];
        g_partials[blockIdx.x] = acc;
    }
}

// ============================================================
// Kernel 4: finalize diff + perplexity.
// ============================================================
__global__ void __launch_bounds__(1024) finalize_kernel(
    float* __restrict__ outDiff, float* __restrict__ outPerp)
{
    __shared__ double sred[1024];
    int tid = threadIdx.x;

    double s = 0.0;
    for (int i = tid; i < GATHER_BLOCKS; i += 1024) s += g_partials[i];
    sred[tid] = s;
    __syncthreads();
    for (int o = 512; o > 0; o >>= 1) {
        if (tid < o) sred[tid] += sred[tid + o];
        __syncthreads();
    }
    if (tid == 0) *outDiff = (float)(sred[0] / (double)QELEMS);
    __syncthreads();

    double ps = 0.0;
    for (int j = tid; j < NEMB; j += 1024) {
        float p  = (float)g_counts[j] * (1.0f / 65536.0f);
        float cl = fmaxf(p, 1e-7f);
        ps += (double)__fmul_rn(p, logf(cl));
    }
    sred[tid] = ps;
    __syncthreads();
    for (int o = 512; o > 0; o >>= 1) {
        if (tid < o) sred[tid] += sred[tid + o];
        __syncthreads();
    }
    if (tid == 0) *outPerp = expf((float)(-sred[0]));
}

// ============================================================
// Output layout (float32): [quantize_st | diff | embed_ind | perplexity]
// ============================================================
extern "C" void kernel_launch(void* const* d_in, const int* in_sizes, int n_in,
                              void* d_out, int out_size) {
    const float* input = (const float*)d_in[0];
    const float* embed = (const float*)d_in[1];
    float* out     = (float*)d_out;
    float* outQ    = out;
    float* outDiff = out + QELEMS;
    float* outInd  = out + QELEMS + 1;
    float* outPerp = out + QELEMS + 1 + NROWS;

    cudaFuncSetAttribute(dist_kernel,
                         cudaFuncAttributeMaxDynamicSharedMemorySize, SMEM_DIST);

    prep_kernel<<<NEMB / 32, 256>>>(embed);
    dist_kernel<<<NROWS / M_CTA, 256, SMEM_DIST>>>(input);
    recheck_kernel<<<NROWS / 8, 256>>>(input, outInd);
    gather_kernel<<<GATHER_BLOCKS, 256>>>(input, outQ);
    finalize_kernel<<<1, 1024>>>(outDiff, outPerp);
}

// round 6
// speedup vs baseline: 220.7761x; 1.1842x over previous
#include <cuda_runtime.h>
#include <cuda_bf16.h>
#include <math.h>
#include <math_constants.h>
#include <stdint.h>

#define DIM    256
#define NEMB   2048
#define NROWS  65536
#define QELEMS (NROWS * DIM)
#define GATHER_BLOCKS 4096
#define CAP    64
#define MARGIN 3.0f

#define M_CTA  256
#define CHUNK  64
#define NCHUNK (NEMB / CHUNK)     // 32

// ---------------- device scratch (no allocations allowed) ----------------
__device__ float         g_embedT[NEMB * DIM];    // fp32 [j][k]
__device__ float         g_sumE2[NEMB];
__device__ __nv_bfloat16 g_embB[NEMB * DIM];      // bf16 [j][k]
__device__ int           g_idx[NROWS];
__device__ int           g_counts[NEMB];
__device__ int           g_candCnt[NROWS];
__device__ int           g_cand[NROWS * CAP];
__device__ double        g_partials[GATHER_BLOCKS];

// ---------------- helpers ----------------
__device__ __forceinline__ uint32_t smem_to_u32(const void* p) {
    uint32_t a;
    asm("{ .reg .u64 t; cvta.to.shared.u64 t, %1; cvt.u32.u64 %0, t; }"
        : "=r"(a) : "l"(p));
    return a;
}
__device__ __forceinline__ uint32_t fenc(float f) {
    uint32_t u = __float_as_uint(f);
    return u ^ ((u >> 31) ? 0xFFFFFFFFu : 0x80000000u);
}
__device__ __forceinline__ float fdec(uint32_t u) {
    return __uint_as_float(u ^ ((u & 0x80000000u) ? 0x80000000u : 0xFFFFFFFFu));
}

__device__ __forceinline__ void ldsm_x4(uint32_t (&r)[4], uint32_t addr) {
    asm volatile("ldmatrix.sync.aligned.m8n8.x4.shared.b16 {%0,%1,%2,%3}, [%4];"
        : "=r"(r[0]), "=r"(r[1]), "=r"(r[2]), "=r"(r[3]) : "r"(addr));
}

__device__ __forceinline__ void mma_bf16(float (&c)[4], const uint32_t (&a)[4],
                                         uint32_t b0, uint32_t b1) {
    asm volatile(
        "mma.sync.aligned.m16n8k16.row.col.f32.bf16.bf16.f32 "
        "{%0,%1,%2,%3}, {%4,%5,%6,%7}, {%8,%9}, {%0,%1,%2,%3};"
        : "+f"(c[0]), "+f"(c[1]), "+f"(c[2]), "+f"(c[3])
        : "r"(a[0]), "r"(a[1]), "r"(a[2]), "r"(a[3]), "r"(b0), "r"(b1));
}

#define CP_ASYNC16(dst, src) \
    asm volatile("cp.async.cg.shared.global [%0], [%1], 16;" \
        :: "r"(dst), "l"(src) : "memory")
#define CP_COMMIT()  asm volatile("cp.async.commit_group;" ::: "memory")
#define CP_WAIT1()   asm volatile("cp.async.wait_group 1;" ::: "memory")
#define CP_WAIT0()   asm volatile("cp.async.wait_group 0;" ::: "memory")

// ============================================================
// Kernel 0: embedT fp32, embB bf16, ||e||^2, zero counts.
// ============================================================
__global__ void __launch_bounds__(256) prep_kernel(const float* __restrict__ embed) {
    __shared__ float psum[8][32];
    const int jl  = threadIdx.x & 31;
    const int seg = threadIdx.x >> 5;
    const int j   = blockIdx.x * 32 + jl;
    const int d0  = seg * 32;

    float s = 0.0f;
    #pragma unroll 8
    for (int dd = 0; dd < 32; dd++) {
        int d = d0 + dd;
        float v = embed[(size_t)d * NEMB + j];
        g_embedT[(size_t)j * DIM + d] = v;
        g_embB[(size_t)j * DIM + d]   = __float2bfloat16_rn(v);
        s = __fadd_rn(s, __fmul_rn(v, v));
    }
    psum[seg][jl] = s;
    __syncthreads();
    if (seg == 0) {
        float t = 0.0f;
        #pragma unroll
        for (int q = 0; q < 8; q++) t += psum[q][jl];
        g_sumE2[j]  = t;
        g_counts[j] = 0;
    }
}

// ============================================================
// Kernel 1: bf16 mma.sync distance, 512 threads / 16 warps.
// CTA: 256 rows. 32 N-chunks of 64 codes. Warp tile 32x32
// (8 M-strips x 2 N-groups).
// ============================================================
#define APITCH 528
#define A_OFF  0
#define B0_OFF (M_CTA * APITCH)
#define B1_OFF (B0_OFF + CHUNK * APITCH)
#define RB_OFF (B1_OFF + CHUNK * APITCH)
#define SMEM_DIST (RB_OFF + M_CTA * 4)          // 203776 bytes

__global__ void __launch_bounds__(512, 1) dist_kernel(const float* __restrict__ input) {
    extern __shared__ __align__(16) char smraw[];
    const uint32_t sbase = smem_to_u32(smraw);
    const uint32_t asU   = sbase + A_OFF;
    unsigned int* sRowBest = (unsigned int*)(smraw + RB_OFF);

    const int tid  = threadIdx.x;
    const int wid  = tid >> 5;
    const int lane = tid & 31;
    const int warp_m = wid >> 1;     // 0..7 : 32-row strip
    const int warp_n = wid & 1;      // 0..1 : 32-col group
    const int row0 = blockIdx.x * M_CTA;

    if (tid < M_CTA) {
        g_candCnt[row0 + tid] = 0;
        sRowBest[tid] = 0xFFFFFFFFu;
    }

    // ---- issue B chunk 0 (cp.async): 64 codes x 512B = 2048 vec16 ----
    {
        const uint32_t bU = sbase + B0_OFF;
        #pragma unroll
        for (int it = 0; it < 4; it++) {
            int idx = tid + it * 512;
            int n = idx >> 5, v = idx & 31;
            const void* src = (const void*)(g_embB + (size_t)n * DIM + v * 8);
            CP_ASYNC16(bU + n * APITCH + v * 16, src);
        }
        CP_COMMIT();
    }

    // ---- load + convert A: 256 rows x 256 fp32 -> bf16 SMEM ----
    {
        const float4* in4 = (const float4*)(input + (size_t)row0 * DIM);
        #pragma unroll
        for (int it = 0; it < 32; it++) {
            int idx = tid + it * 512;        // 16384 float4
            int r = idx >> 6, v = idx & 63;
            float4 f = in4[idx];
            __nv_bfloat162 p0 = __floats2bfloat162_rn(f.x, f.y);
            __nv_bfloat162 p1 = __floats2bfloat162_rn(f.z, f.w);
            uint2 st;
            st.x = *reinterpret_cast<unsigned int*>(&p0);
            st.y = *reinterpret_cast<unsigned int*>(&p1);
            *(uint2*)(smraw + A_OFF + r * APITCH + v * 8) = st;
        }
    }

    // rows owned by this thread: lrow[mi][h]
    int lrow[2][2];
    #pragma unroll
    for (int mi = 0; mi < 2; mi++)
        #pragma unroll
        for (int h = 0; h < 2; h++)
            lrow[mi][h] = warp_m * 32 + mi * 16 + (lane >> 2) + h * 8;

    // A fragment base (per mi add mi*16*APITCH)
    const uint32_t a_base = asU + (warp_m * 32 + (lane & 15)) * APITCH
                          + ((lane >> 4) & 1) * 16;
    // B fragment base (two 16-code groups at +0 and +16*APITCH)
    const uint32_t b_off = (warp_n * 32 + (lane & 7) + ((lane & 16) >> 1)) * APITCH
                         + ((lane >> 3) & 1) * 16;

    #pragma unroll 1
    for (int c = 0; c < NCHUNK; c++) {
        const int j0 = c * CHUNK;
        if (c + 1 < NCHUNK) {
            const uint32_t bU = sbase + (((c + 1) & 1) ? B1_OFF : B0_OFF);
            #pragma unroll
            for (int it = 0; it < 4; it++) {
                int idx = tid + it * 512;
                int n = idx >> 5, v = idx & 31;
                const void* src = (const void*)(g_embB + (size_t)(j0 + CHUNK + n) * DIM + v * 8);
                CP_ASYNC16(bU + n * APITCH + v * 16, src);
            }
            CP_COMMIT();
            CP_WAIT1();
        } else {
            CP_WAIT0();
        }
        __syncthreads();

        const uint32_t bbase = sbase + ((c & 1) ? B1_OFF : B0_OFF) + b_off;

        float acc[2][4][4];
        #pragma unroll
        for (int mi = 0; mi < 2; mi++)
            #pragma unroll
            for (int ni = 0; ni < 4; ni++)
                #pragma unroll
                for (int q = 0; q < 4; q++) acc[mi][ni][q] = 0.0f;

        #pragma unroll 4
        for (int ks = 0; ks < 16; ks++) {
            uint32_t af[2][4], bf[2][4];
            ldsm_x4(af[0], a_base + ks * 32);
            ldsm_x4(af[1], a_base + 16 * APITCH + ks * 32);
            ldsm_x4(bf[0], bbase + ks * 32);
            ldsm_x4(bf[1], bbase + 16 * APITCH + ks * 32);
            #pragma unroll
            for (int mi = 0; mi < 2; mi++) {
                mma_bf16(acc[mi][0], af[mi], bf[0][0], bf[0][1]);
                mma_bf16(acc[mi][1], af[mi], bf[0][2], bf[0][3]);
                mma_bf16(acc[mi][2], af[mi], bf[1][0], bf[1][1]);
                mma_bf16(acc[mi][3], af[mi], bf[1][2], bf[1][3]);
            }
        }

        // ---- keys d = se2 - 2*dot (in place); per-(mi,h) minima ----
        float lmin[2][2] = {{CUDART_INF_F, CUDART_INF_F},
                            {CUDART_INF_F, CUDART_INF_F}};
        #pragma unroll
        for (int ni = 0; ni < 4; ni++) {
            int jb = j0 + warp_n * 32 + ni * 8 + ((lane & 3) << 1);
            float se0 = __ldg(&g_sumE2[jb]);
            float se1 = __ldg(&g_sumE2[jb + 1]);
            #pragma unroll
            for (int mi = 0; mi < 2; mi++) {
                #pragma unroll
                for (int q = 0; q < 4; q++) {
                    float d = fmaf(acc[mi][ni][q], -2.0f, (q & 1) ? se1 : se0);
                    acc[mi][ni][q] = d;
                    lmin[mi][q >> 1] = fminf(lmin[mi][q >> 1], d);
                }
            }
        }
        #pragma unroll
        for (int mi = 0; mi < 2; mi++)
            #pragma unroll
            for (int h = 0; h < 2; h++)
                atomicMin(&sRowBest[lrow[mi][h]], fenc(lmin[mi][h]));
        __syncthreads();

        // margin test vs row-global running best, append candidates
        #pragma unroll
        for (int mi = 0; mi < 2; mi++) {
            #pragma unroll
            for (int h = 0; h < 2; h++) {
                float rb = fdec(sRowBest[lrow[mi][h]]) + MARGIN;
                int g = row0 + lrow[mi][h];
                #pragma unroll
                for (int ni = 0; ni < 4; ni++) {
                    #pragma unroll
                    for (int qq = 0; qq < 2; qq++) {
                        float d = acc[mi][ni][h * 2 + qq];
                        if (d < rb) {
                            int pos = atomicAdd(&g_candCnt[g], 1);
                            if (pos < CAP)
                                g_cand[(size_t)g * CAP + pos] =
                                    j0 + warp_n * 32 + ni * 8 + ((lane & 3) << 1) + qq;
                        }
                    }
                }
            }
        }
        __syncthreads();
    }
}

// ============================================================
// Kernel 2: exact fp32 re-check over candidates (warp per row).
// ============================================================
__global__ void __launch_bounds__(256) recheck_kernel(
    const float* __restrict__ input, float* __restrict__ indOutF)
{
    __shared__ float xs[8][256];
    const int w = threadIdx.x >> 5, l = threadIdx.x & 31;
    const int row = blockIdx.x * 8 + w;

    const float4* xr4 = (const float4*)(input + (size_t)row * DIM);
    float4 xa = xr4[l];
    float4 xb = xr4[l + 32];
    *(float4*)&xs[w][l * 4]       = xa;
    *(float4*)&xs[w][128 + l * 4] = xb;
    __syncwarp();

    float xr[8];
    #pragma unroll
    for (int u = 0; u < 8; u++) xr[u] = xs[w][l * 8 + u];

    float p2 = 0.0f;
    #pragma unroll
    for (int u = 0; u < 8; u++) p2 = fmaf(xr[u], xr[u], p2);
    #pragma unroll
    for (int o = 16; o > 0; o >>= 1) p2 += __shfl_xor_sync(0xffffffffu, p2, o);
    const float sx2 = p2;

    const int cnt = g_candCnt[row];
    float bd = CUDART_INF_F; int bi = 0x7fffffff;

    const int limit = (cnt <= CAP) ? cnt : NEMB;
    for (int c = 0; c < limit; c++) {
        int j = (cnt <= CAP) ? g_cand[(size_t)row * CAP + c] : c;
        const float4* e4 = (const float4*)(g_embedT + (size_t)j * DIM);
        float4 e0 = e4[l * 2], e1 = e4[l * 2 + 1];
        float p = 0.0f;
        p = fmaf(xr[0], e0.x, p); p = fmaf(xr[1], e0.y, p);
        p = fmaf(xr[2], e0.z, p); p = fmaf(xr[3], e0.w, p);
        p = fmaf(xr[4], e1.x, p); p = fmaf(xr[5], e1.y, p);
        p = fmaf(xr[6], e1.z, p); p = fmaf(xr[7], e1.w, p);
        #pragma unroll
        for (int o = 16; o > 0; o >>= 1) p += __shfl_xor_sync(0xffffffffu, p, o);
        float d = __fadd_rn(__fsub_rn(sx2, __fmul_rn(2.0f, p)), __ldg(&g_sumE2[j]));
        if (d < bd || (d == bd && j < bi)) { bd = d; bi = j; }
    }

    if (l == 0) {
        g_idx[row]   = bi;
        indOutF[row] = (float)bi;
        atomicAdd(&g_counts[bi], 1);
    }
}

// ============================================================
// Kernel 3: gather codes, STE output, diff partials (16 f/thread).
// ============================================================
__global__ void __launch_bounds__(256) gather_kernel(
    const float* __restrict__ input, float* __restrict__ outQ)
{
    __shared__ double wsum[8];
    const int t = blockIdx.x * 256 + threadIdx.x;
    const int n = t >> 4;                            // 16 threads per row
    const int ind = g_idx[n];
    const int v0 = (t & 15) * 4;

    const float4* erow = (const float4*)(g_embedT + (size_t)ind * DIM);
    const float4* xrow = (const float4*)(input + (size_t)n * DIM);
    float4* qrow = (float4*)(outQ + (size_t)n * DIM);

    float4 e[4], x[4];
    #pragma unroll
    for (int u = 0; u < 4; u++) x[u] = xrow[v0 + u];
    #pragma unroll
    for (int u = 0; u < 4; u++) e[u] = __ldg(&erow[v0 + u]);

    double s = 0.0;
    #pragma unroll
    for (int u = 0; u < 4; u++) {
        float dx0 = __fsub_rn(e[u].x, x[u].x);
        float dx1 = __fsub_rn(e[u].y, x[u].y);
        float dx2 = __fsub_rn(e[u].z, x[u].z);
        float dx3 = __fsub_rn(e[u].w, x[u].w);
        float4 q;
        q.x = __fadd_rn(x[u].x, dx0);
        q.y = __fadd_rn(x[u].y, dx1);
        q.z = __fadd_rn(x[u].z, dx2);
        q.w = __fadd_rn(x[u].w, dx3);
        qrow[v0 + u] = q;
        s += (double)__fmul_rn(dx0, dx0) + (double)__fmul_rn(dx1, dx1)
           + (double)__fmul_rn(dx2, dx2) + (double)__fmul_rn(dx3, dx3);
    }

    #pragma unroll
    for (int o = 16; o > 0; o >>= 1) s += __shfl_xor_sync(0xffffffffu, s, o);
    if ((threadIdx.x & 31) == 0) wsum[threadIdx.x >> 5] = s;
    __syncthreads();
    if (threadIdx.x == 0) {
        double acc = 0.0;
        #pragma unroll
        for (int i = 0; i < 8; i++) acc += wsum[i];
        g_partials[blockIdx.x] = acc;
    }
}

// ============================================================
// Kernel 4: finalize diff + perplexity.
// ============================================================
__global__ void __launch_bounds__(1024) finalize_kernel(
    float* __restrict__ outDiff, float* __restrict__ outPerp)
{
    __shared__ double sred[1024];
    int tid = threadIdx.x;

    double s = 0.0;
    for (int i = tid; i < GATHER_BLOCKS; i += 1024) s += g_partials[i];
    sred[tid] = s;
    __syncthreads();
    for (int o = 512; o > 0; o >>= 1) {
        if (tid < o) sred[tid] += sred[tid + o];
        __syncthreads();
    }
    if (tid == 0) *outDiff = (float)(sred[0] / (double)QELEMS);
    __syncthreads();

    double ps = 0.0;
    for (int j = tid; j < NEMB; j += 1024) {
        float p  = (float)g_counts[j] * (1.0f / 65536.0f);
        float cl = fmaxf(p, 1e-7f);
        ps += (double)__fmul_rn(p, logf(cl));
    }
    sred[tid] = ps;
    __syncthreads();
    for (int o = 512; o > 0; o >>= 1) {
        if (tid < o) sred[tid] += sred[tid + o];
        __syncthreads();
    }
    if (tid == 0) *outPerp = expf((float)(-sred[0]));
}

// ============================================================
// Output layout (float32): [quantize_st | diff | embed_ind | perplexity]
// ============================================================
extern "C" void kernel_launch(void* const* d_in, const int* in_sizes, int n_in,
                              void* d_out, int out_size) {
    const float* input = (const float*)d_in[0];
    const float* embed = (const float*)d_in[1];
    float* out     = (float*)d_out;
    float* outQ    = out;
    float* outDiff = out + QELEMS;
    float* outInd  = out + QELEMS + 1;
    float* outPerp = out + QELEMS + 1 + NROWS;

    cudaFuncSetAttribute(dist_kernel,
                         cudaFuncAttributeMaxDynamicSharedMemorySize, SMEM_DIST);

    prep_kernel<<<NEMB / 32, 256>>>(embed);
    dist_kernel<<<NROWS / M_CTA, 512, SMEM_DIST>>>(input);
    recheck_kernel<<<NROWS / 8, 256>>>(input, outInd);
    gather_kernel<<<GATHER_BLOCKS, 256>>>(input, outQ);
    finalize_kernel<<<1, 1024>>>(outDiff, outPerp);
}